// round 2
// baseline (speedup 1.0000x reference)
#include <cuda_runtime.h>
#include <cuda_bf16.h>
#include <cstdint>

#define D 128
#define MAXN 100000
#define BM 64

// Scratch buffers (device globals: allocation-free rule)
__device__ float g_agg[(size_t)MAXN * D];
__device__ float g_h  [(size_t)MAXN * D];
__device__ float g_t  [(size_t)MAXN * D];

// ---------------- copy: agg = x (self term, eps=0 so (1+eps)*x = x) --------
__global__ void copy_kernel(const float* __restrict__ src, float* __restrict__ dst, int n4) {
    int i = blockIdx.x * blockDim.x + threadIdx.x;
    int stride = gridDim.x * blockDim.x;
    const float4* s = reinterpret_cast<const float4*>(src);
    float4* d = reinterpret_cast<float4*>(dst);
    for (; i < n4; i += stride) d[i] = s[i];
}

// ---------------- scatter: agg[dst] += x[src], one warp per edge -----------
// edge_index is int32 (JAX default x64-disabled downcasts int64 -> int32),
// layout [2, E]: row 0 = src, row 1 = dst.
__global__ void scatter_kernel(const float* __restrict__ x,
                               const int* __restrict__ ei,
                               float* __restrict__ agg, int E) {
    int warp = (blockIdx.x * blockDim.x + threadIdx.x) >> 5;
    int lane = threadIdx.x & 31;
    if (warp >= E) return;
    int s = ei[warp];       // src row
    int d = ei[E + warp];   // dst row
    const float4 v = *reinterpret_cast<const float4*>(x + (size_t)s * D + lane * 4);
    float* p = agg + (size_t)d * D + lane * 4;
    asm volatile("red.global.add.v4.f32 [%0], {%1,%2,%3,%4};"
                 :: "l"(p), "f"(v.x), "f"(v.y), "f"(v.z), "f"(v.w) : "memory");
}

// ---------------- GEMM: C = relu(A[M,128] @ W[128,128] + b) ----------------
// Block: 256 threads, computes 64 rows x 128 cols. Thread tile 4x8.
__global__ __launch_bounds__(256) void gemm_relu_kernel(
    const float* __restrict__ A, const float* __restrict__ W,
    const float* __restrict__ bias, float* __restrict__ C, int M) {
    __shared__ float As[BM][32];
    __shared__ float Ws[32][D];

    int tid = threadIdx.x;
    int tx = tid & 15;       // 16 column groups of 8
    int ty = tid >> 4;       // 16 row groups of 4
    int row0 = blockIdx.x * BM;

    float acc[4][8];
    #pragma unroll
    for (int i = 0; i < 4; i++)
        #pragma unroll
        for (int j = 0; j < 8; j++) acc[i][j] = 0.0f;

    for (int k0 = 0; k0 < D; k0 += 32) {
        // Load A tile 64x32 (8 floats / thread)
        {
            int r = tid >> 2;            // 0..63
            int kk = (tid & 3) * 8;      // 0,8,16,24
            int grow = row0 + r;
            float4 v0, v1;
            if (grow < M) {
                const float* ap = A + (size_t)grow * D + k0 + kk;
                v0 = *reinterpret_cast<const float4*>(ap);
                v1 = *reinterpret_cast<const float4*>(ap + 4);
            } else {
                v0 = make_float4(0.f, 0.f, 0.f, 0.f);
                v1 = v0;
            }
            *reinterpret_cast<float4*>(&As[r][kk])     = v0;
            *reinterpret_cast<float4*>(&As[r][kk + 4]) = v1;
        }
        // Load W tile 32x128 (16 floats / thread)
        {
            int r = tid >> 3;            // 0..31
            int c = (tid & 7) * 16;      // 0..112
            const float4* wp = reinterpret_cast<const float4*>(W + (size_t)(k0 + r) * D + c);
            float4* sp = reinterpret_cast<float4*>(&Ws[r][c]);
            sp[0] = wp[0]; sp[1] = wp[1]; sp[2] = wp[2]; sp[3] = wp[3];
        }
        __syncthreads();

        #pragma unroll
        for (int kk = 0; kk < 32; kk++) {
            float a[4];
            #pragma unroll
            for (int i = 0; i < 4; i++) a[i] = As[ty * 4 + i][kk];
            float4 w0 = *reinterpret_cast<float4*>(&Ws[kk][tx * 8]);
            float4 w1 = *reinterpret_cast<float4*>(&Ws[kk][tx * 8 + 4]);
            float w[8] = {w0.x, w0.y, w0.z, w0.w, w1.x, w1.y, w1.z, w1.w};
            #pragma unroll
            for (int i = 0; i < 4; i++)
                #pragma unroll
                for (int j = 0; j < 8; j++)
                    acc[i][j] = fmaf(a[i], w[j], acc[i][j]);
        }
        __syncthreads();
    }

    // Epilogue: + bias, relu, store
    float4 b0 = *reinterpret_cast<const float4*>(bias + tx * 8);
    float4 b1 = *reinterpret_cast<const float4*>(bias + tx * 8 + 4);
    float b[8] = {b0.x, b0.y, b0.z, b0.w, b1.x, b1.y, b1.z, b1.w};

    #pragma unroll
    for (int i = 0; i < 4; i++) {
        int row = row0 + ty * 4 + i;
        if (row >= M) continue;
        float4 o0, o1;
        o0.x = fmaxf(acc[i][0] + b[0], 0.f);
        o0.y = fmaxf(acc[i][1] + b[1], 0.f);
        o0.z = fmaxf(acc[i][2] + b[2], 0.f);
        o0.w = fmaxf(acc[i][3] + b[3], 0.f);
        o1.x = fmaxf(acc[i][4] + b[4], 0.f);
        o1.y = fmaxf(acc[i][5] + b[5], 0.f);
        o1.z = fmaxf(acc[i][6] + b[6], 0.f);
        o1.w = fmaxf(acc[i][7] + b[7], 0.f);
        float* cp = C + (size_t)row * D + tx * 8;
        *reinterpret_cast<float4*>(cp)     = o0;
        *reinterpret_cast<float4*>(cp + 4) = o1;
    }
}

extern "C" void kernel_launch(void* const* d_in, const int* in_sizes, int n_in,
                              void* d_out, int out_size) {
    const float* x  = (const float*)d_in[0];
    const int*   ei = (const int*)d_in[1];   // int32: JAX x64-disabled
    const float* W1[3] = {(const float*)d_in[2],  (const float*)d_in[6],  (const float*)d_in[10]};
    const float* b1[3] = {(const float*)d_in[3],  (const float*)d_in[7],  (const float*)d_in[11]};
    const float* W2[3] = {(const float*)d_in[4],  (const float*)d_in[8],  (const float*)d_in[12]};
    const float* b2[3] = {(const float*)d_in[5],  (const float*)d_in[9],  (const float*)d_in[13]};

    int M = in_sizes[0] / D;
    int E = in_sizes[1] / 2;

    float *agg, *h, *t;
    cudaGetSymbolAddress((void**)&agg, g_agg);
    cudaGetSymbolAddress((void**)&h,   g_h);
    cudaGetSymbolAddress((void**)&t,   g_t);

    int n4 = M * D / 4;
    int copyBlocks = (n4 + 255) / 256;
    if (copyBlocks > 8192) copyBlocks = 8192;
    int scatterBlocks = (int)(((long long)E * 32 + 255) / 256);   // one warp per edge
    int gemmBlocks = (M + BM - 1) / BM;

    const float* cur = x;
    float* outs[3] = {t, t, (float*)d_out};

    for (int l = 0; l < 3; l++) {
        copy_kernel<<<copyBlocks, 256>>>(cur, agg, n4);
        scatter_kernel<<<scatterBlocks, 256>>>(cur, ei, agg, E);
        gemm_relu_kernel<<<gemmBlocks, 256>>>(agg, W1[l], b1[l], h, M);
        gemm_relu_kernel<<<gemmBlocks, 256>>>(h, W2[l], b2[l], outs[l], M);
        cur = outs[l];
    }
}

// round 4
// speedup vs baseline: 1.5009x; 1.5009x over previous
#include <cuda_runtime.h>
#include <cuda_bf16.h>
#include <cstdint>

#define D 128
#define MAXN 100000

// ---------------- device scratch (allocation-free rule) --------------------
__device__ float g_agg[(size_t)MAXN * D];
__device__ float g_h  [(size_t)MAXN * D];
__device__ float g_t  [(size_t)MAXN * D];
// 6 GEMMs x (hi + lo) W^T images, padded row-major [n][136] bf16
#define IMG_ELEMS 17408            // 128 * 136
__device__ __nv_bfloat16 g_Wimg[6 * 2 * IMG_ELEMS];

// ---------------- smem layout for gemm (bytes) ------------------------------
#define ROWB      272              // 136 bf16 per row
#define IMG_BYTES 34816            // 128 * 272
#define OFF_WHI   0
#define OFF_WLO   34816
#define OFF_AHI   69632
#define OFF_ALO   104448
#define OFF_BIAS  139264
#define SMEM_TOTAL 139776

__device__ __forceinline__ uint32_t smem_u32(const void* p) {
    uint32_t a;
    asm("{ .reg .u64 t; cvta.to.shared.u64 t, %1; cvt.u32.u64 %0, t; }" : "=r"(a) : "l"(p));
    return a;
}

#define LDSM_X4(r0, r1, r2, r3, addr) \
    asm volatile("ldmatrix.sync.aligned.m8n8.x4.shared.b16 {%0,%1,%2,%3}, [%4];" \
                 : "=r"(r0), "=r"(r1), "=r"(r2), "=r"(r3) : "r"(addr))
#define LDSM_X2(r0, r1, addr) \
    asm volatile("ldmatrix.sync.aligned.m8n8.x2.shared.b16 {%0,%1}, [%2];" \
                 : "=r"(r0), "=r"(r1) : "r"(addr))

__device__ __forceinline__ void mma_bf16(float* c, const uint32_t* a, uint32_t b0, uint32_t b1) {
    asm volatile(
        "mma.sync.aligned.m16n8k16.row.col.f32.bf16.bf16.f32 "
        "{%0,%1,%2,%3}, {%4,%5,%6,%7}, {%8,%9}, {%0,%1,%2,%3};"
        : "+f"(c[0]), "+f"(c[1]), "+f"(c[2]), "+f"(c[3])
        : "r"(a[0]), "r"(a[1]), "r"(a[2]), "r"(a[3]), "r"(b0), "r"(b1));
}

// ---------------- copy: agg = x (self term, eps=0) ---------------------------
__global__ void copy_kernel(const float* __restrict__ src, float* __restrict__ dst, int n4) {
    int i = blockIdx.x * blockDim.x + threadIdx.x;
    int stride = gridDim.x * blockDim.x;
    const float4* s = reinterpret_cast<const float4*>(src);
    float4* d = reinterpret_cast<float4*>(dst);
    for (; i < n4; i += stride) d[i] = s[i];
}

// ---------------- scatter: agg[dst] += x[src], one warp per edge ------------
__global__ void scatter_kernel(const float* __restrict__ x,
                               const int* __restrict__ ei,
                               float* __restrict__ agg, int E) {
    int warp = (blockIdx.x * blockDim.x + threadIdx.x) >> 5;
    int lane = threadIdx.x & 31;
    if (warp >= E) return;
    int s = ei[warp];
    int d = ei[E + warp];
    const float4 v = *reinterpret_cast<const float4*>(x + (size_t)s * D + lane * 4);
    float* p = agg + (size_t)d * D + lane * 4;
    asm volatile("red.global.add.v4.f32 [%0], {%1,%2,%3,%4};"
                 :: "l"(p), "f"(v.x), "f"(v.y), "f"(v.z), "f"(v.w) : "memory");
}

// ---------------- W prep: W[k][n] fp32 -> W^T hi/lo bf16 padded images ------
struct WPtrs { const float* p[6]; };
__global__ void wprep_kernel(WPtrs wp, __nv_bfloat16* img) {
    int t = blockIdx.x * blockDim.x + threadIdx.x;
    if (t >= 6 * 16384) return;
    int g = t >> 14;
    int rem = t & 16383;
    int n = rem >> 7;
    int k = rem & 127;
    float w = wp.p[g][k * D + n];
    __nv_bfloat16 hi = __float2bfloat16(w);
    float r = w - __bfloat162float(hi);
    __nv_bfloat16 lo = __float2bfloat16(r);
    size_t base = (size_t)g * 2 * IMG_ELEMS;
    img[base + n * 136 + k]             = hi;
    img[base + IMG_ELEMS + n * 136 + k] = lo;
}

// ---------------- GEMM via mma.sync bf16, 3-term split ----------------------
// Block: 256 threads (8 warps), one 128x128 output tile.
// Warp w: rows w*16 .. w*16+15, all 128 cols.
__global__ __launch_bounds__(256, 1) void gemm_mma_kernel(
    const float* __restrict__ A, const __nv_bfloat16* __restrict__ Wimg,
    const float* __restrict__ bias, float* __restrict__ C, int M) {
    extern __shared__ char smem[];
    uint32_t sb = smem_u32(smem);
    int tid = threadIdx.x, wid = tid >> 5, lane = tid & 31;
    int row0 = blockIdx.x << 7;

    // Load W hi+lo images (69632 B = 4352 uint4, 17/thread)
    {
        const uint4* src = reinterpret_cast<const uint4*>(Wimg);
        uint4* dst = reinterpret_cast<uint4*>(smem);
        #pragma unroll
        for (int i = 0; i < 17; i++) dst[tid + i * 256] = src[tid + i * 256];
    }
    if (tid < 32)
        reinterpret_cast<float4*>(smem + OFF_BIAS)[tid] =
            reinterpret_cast<const float4*>(bias)[tid];

    // Convert A tile (128 rows x 128 k, fp32) -> hi/lo bf16 padded images
    #pragma unroll
    for (int i = 0; i < 8; i++) {
        int ci = tid + i * 256;          // 0..2047
        int row = ci >> 4;
        int kg = ci & 15;                // k group of 8
        int grow = row0 + row;
        uint32_t hi[4] = {0, 0, 0, 0}, lo[4] = {0, 0, 0, 0};
        if (grow < M) {
            const float4* ap = reinterpret_cast<const float4*>(A + (size_t)grow * D + kg * 8);
            float4 v0 = ap[0], v1 = ap[1];
            float a0[8] = {v0.x, v0.y, v0.z, v0.w, v1.x, v1.y, v1.z, v1.w};
            #pragma unroll
            for (int j = 0; j < 4; j++) {
                __nv_bfloat162 h = __floats2bfloat162_rn(a0[2 * j], a0[2 * j + 1]);
                float r0 = a0[2 * j]     - __bfloat162float(h.x);
                float r1 = a0[2 * j + 1] - __bfloat162float(h.y);
                __nv_bfloat162 l = __floats2bfloat162_rn(r0, r1);
                hi[j] = *reinterpret_cast<uint32_t*>(&h);
                lo[j] = *reinterpret_cast<uint32_t*>(&l);
            }
        }
        uint32_t off = row * ROWB + kg * 16;
        *reinterpret_cast<uint4*>(smem + OFF_AHI + off) = make_uint4(hi[0], hi[1], hi[2], hi[3]);
        *reinterpret_cast<uint4*>(smem + OFF_ALO + off) = make_uint4(lo[0], lo[1], lo[2], lo[3]);
    }
    __syncthreads();

    // Accumulators: 16 n-blocks x 4 regs
    float acc[16][4];
    #pragma unroll
    for (int nb = 0; nb < 16; nb++)
        #pragma unroll
        for (int j = 0; j < 4; j++) acc[nb][j] = 0.0f;

    // ldmatrix lane address bases (row stride 272B is conflict-free: 68 words % 32 = 4)
    // A x4: lanes 0-7 rows 0-7 k0, 8-15 rows 8-15 k0, 16-23 rows 0-7 k0+8, 24-31 rows 8-15 k0+8
    uint32_t aBase = sb + OFF_AHI + (wid * 16 + (lane & 15)) * ROWB + (lane >> 4) * 16;
    // B x2: lanes 0-7 rows n0..n0+7 k0, lanes 8-15 rows n0.. k0+8 (lanes 16-31 unused)
    uint32_t wBase = sb + OFF_WHI + (lane & 7) * ROWB + ((lane & 8) ? 16 : 0);

    #pragma unroll
    for (int kc = 0; kc < 8; kc++) {          // K chunks of 16
        uint32_t aHi[4], aLo[4];
        uint32_t aAddr = aBase + kc * 32;
        LDSM_X4(aHi[0], aHi[1], aHi[2], aHi[3], aAddr);
        LDSM_X4(aLo[0], aLo[1], aLo[2], aLo[3], aAddr + (OFF_ALO - OFF_AHI));
        #pragma unroll
        for (int nb = 0; nb < 16; nb++) {
            uint32_t bAddr = wBase + nb * (8 * ROWB) + kc * 32;
            uint32_t bHi0, bHi1, bLo0, bLo1;
            LDSM_X2(bHi0, bHi1, bAddr);
            LDSM_X2(bLo0, bLo1, bAddr + IMG_BYTES);
            mma_bf16(acc[nb], aHi, bHi0, bHi1);
            mma_bf16(acc[nb], aHi, bLo0, bLo1);
            mma_bf16(acc[nb], aLo, bHi0, bHi1);
        }
    }

    // Epilogue: c0/c1 -> row r0, cols cb, cb+1 ; c2/c3 -> row r0+8
    const float* sBias = reinterpret_cast<const float*>(smem + OFF_BIAS);
    int r0 = row0 + wid * 16 + (lane >> 2);
    int r1 = r0 + 8;
    #pragma unroll
    for (int nb = 0; nb < 16; nb++) {
        int cb = nb * 8 + (lane & 3) * 2;
        float b0 = sBias[cb], b1 = sBias[cb + 1];
        if (r0 < M) {
            float2 o;
            o.x = fmaxf(acc[nb][0] + b0, 0.f);
            o.y = fmaxf(acc[nb][1] + b1, 0.f);
            *reinterpret_cast<float2*>(C + (size_t)r0 * D + cb) = o;
        }
        if (r1 < M) {
            float2 o;
            o.x = fmaxf(acc[nb][2] + b0, 0.f);
            o.y = fmaxf(acc[nb][3] + b1, 0.f);
            *reinterpret_cast<float2*>(C + (size_t)r1 * D + cb) = o;
        }
    }
}

extern "C" void kernel_launch(void* const* d_in, const int* in_sizes, int n_in,
                              void* d_out, int out_size) {
    const float* x  = (const float*)d_in[0];
    const int*   ei = (const int*)d_in[1];   // int32 (JAX x64 disabled)
    const float* W1[3] = {(const float*)d_in[2],  (const float*)d_in[6],  (const float*)d_in[10]};
    const float* b1[3] = {(const float*)d_in[3],  (const float*)d_in[7],  (const float*)d_in[11]};
    const float* W2[3] = {(const float*)d_in[4],  (const float*)d_in[8],  (const float*)d_in[12]};
    const float* b2[3] = {(const float*)d_in[5],  (const float*)d_in[9],  (const float*)d_in[13]};

    int M = in_sizes[0] / D;
    int E = in_sizes[1] / 2;

    float *agg, *h, *t;
    __nv_bfloat16* wimg;
    cudaGetSymbolAddress((void**)&agg,  g_agg);
    cudaGetSymbolAddress((void**)&h,    g_h);
    cudaGetSymbolAddress((void**)&t,    g_t);
    cudaGetSymbolAddress((void**)&wimg, g_Wimg);

    cudaFuncSetAttribute(gemm_mma_kernel, cudaFuncAttributeMaxDynamicSharedMemorySize, SMEM_TOTAL);

    // Prepare W images (order: W1_0, W2_0, W1_1, W2_1, W1_2, W2_2)
    WPtrs wp;
    wp.p[0] = W1[0]; wp.p[1] = W2[0];
    wp.p[2] = W1[1]; wp.p[3] = W2[1];
    wp.p[4] = W1[2]; wp.p[5] = W2[2];
    wprep_kernel<<<(6 * 16384 + 255) / 256, 256>>>(wp, wimg);

    int n4 = M * D / 4;
    int copyBlocks = (n4 + 255) / 256;
    if (copyBlocks > 8192) copyBlocks = 8192;
    int scatterBlocks = (int)(((long long)E * 32 + 255) / 256);
    int gemmBlocks = (M + 127) / 128;

    const float* cur = x;
    float* outs[3] = {t, t, (float*)d_out};

    for (int l = 0; l < 3; l++) {
        copy_kernel<<<copyBlocks, 256>>>(cur, agg, n4);
        scatter_kernel<<<scatterBlocks, 256>>>(cur, ei, agg, E);
        gemm_mma_kernel<<<gemmBlocks, 256, SMEM_TOTAL>>>(
            agg, wimg + (size_t)(2 * l) * 2 * IMG_ELEMS, b1[l], h, M);
        gemm_mma_kernel<<<gemmBlocks, 256, SMEM_TOTAL>>>(
            h, wimg + (size_t)(2 * l + 1) * 2 * IMG_ELEMS, b2[l], outs[l], M);
        cur = outs[l];
    }
}

// round 5
// speedup vs baseline: 2.6118x; 1.7401x over previous
#include <cuda_runtime.h>
#include <cuda_bf16.h>
#include <cstdint>

#define D 128
#define MAXN 100000
#define MAXE 1600000

// ---------------- device scratch (allocation-free rule) --------------------
__device__ float g_agg[(size_t)MAXN * D];
__device__ float g_h  [(size_t)MAXN * D];
__device__ float g_t  [(size_t)MAXN * D];
// CSR scratch
__device__ int g_cnt[MAXN];
__device__ int g_off[MAXN + 1];
__device__ int g_cur[MAXN];
__device__ int g_csr[MAXE];
__device__ int g_bsum[128];
__device__ int g_bbase[128];
// 6 GEMMs x (hi + lo) W^T images, padded row-major [n][136] bf16
#define IMG_ELEMS 17408            // 128 * 136
__device__ __nv_bfloat16 g_Wimg[6 * 2 * IMG_ELEMS];

// ---------------- smem layout for gemm (bytes) ------------------------------
#define ROWB      272              // 136 bf16 per row
#define IMG_BYTES 34816            // 128 * 272
#define OFF_WHI   0
#define OFF_WLO   34816
#define OFF_AHI   69632
#define OFF_ALO   104448
#define OFF_BIAS  139264
#define SMEM_TOTAL 139776

__device__ __forceinline__ uint32_t smem_u32(const void* p) {
    uint32_t a;
    asm("{ .reg .u64 t; cvta.to.shared.u64 t, %1; cvt.u32.u64 %0, t; }" : "=r"(a) : "l"(p));
    return a;
}

#define LDSM_X4(r0, r1, r2, r3, addr) \
    asm volatile("ldmatrix.sync.aligned.m8n8.x4.shared.b16 {%0,%1,%2,%3}, [%4];" \
                 : "=r"(r0), "=r"(r1), "=r"(r2), "=r"(r3) : "r"(addr))
#define LDSM_X2(r0, r1, addr) \
    asm volatile("ldmatrix.sync.aligned.m8n8.x2.shared.b16 {%0,%1}, [%2];" \
                 : "=r"(r0), "=r"(r1) : "r"(addr))

__device__ __forceinline__ void mma_bf16(float* c, const uint32_t* a, uint32_t b0, uint32_t b1) {
    asm volatile(
        "mma.sync.aligned.m16n8k16.row.col.f32.bf16.bf16.f32 "
        "{%0,%1,%2,%3}, {%4,%5,%6,%7}, {%8,%9}, {%0,%1,%2,%3};"
        : "+f"(c[0]), "+f"(c[1]), "+f"(c[2]), "+f"(c[3])
        : "r"(a[0]), "r"(a[1]), "r"(a[2]), "r"(a[3]), "r"(b0), "r"(b1));
}

// ================= CSR build =================================================
__global__ void zero_cnt_kernel(int* cnt, int N) {
    int i = blockIdx.x * blockDim.x + threadIdx.x;
    if (i < N) cnt[i] = 0;
}

__global__ void hist_kernel(const int* __restrict__ ei, int* cnt, int E) {
    int e = blockIdx.x * blockDim.x + threadIdx.x;
    if (e < E) atomicAdd(&cnt[ei[E + e]], 1);
}

// block sums over chunks of 1024
__global__ void scan1_kernel(const int* __restrict__ cnt, int* bsum, int N) {
    __shared__ int sh[256];
    int t = threadIdx.x;
    int base = blockIdx.x * 1024 + t * 4;
    int s = 0;
    #pragma unroll
    for (int i = 0; i < 4; i++) { int idx = base + i; if (idx < N) s += cnt[idx]; }
    sh[t] = s;
    __syncthreads();
    for (int off = 128; off > 0; off >>= 1) {
        if (t < off) sh[t] += sh[t + off];
        __syncthreads();
    }
    if (t == 0) bsum[blockIdx.x] = sh[0];
}

// exclusive scan of block sums (NB <= 128), single block of 128
__global__ void scan2_kernel(const int* __restrict__ bsum, int* bbase, int NB,
                             int* off, int N, int E) {
    __shared__ int sh[128];
    int t = threadIdx.x;
    int v = (t < NB) ? bsum[t] : 0;
    sh[t] = v;
    __syncthreads();
    #pragma unroll
    for (int d = 1; d < 128; d <<= 1) {
        int u = (t >= d) ? sh[t - d] : 0;
        __syncthreads();
        sh[t] += u;
        __syncthreads();
    }
    if (t < NB) bbase[t] = sh[t] - v;   // exclusive
    if (t == 0) off[N] = E;
}

// per-element exclusive prefix within chunk + block base
__global__ void scan3_kernel(const int* __restrict__ cnt, const int* __restrict__ bbase,
                             int* off, int* cur, int N) {
    __shared__ int sh[256];
    int t = threadIdx.x;
    int base = blockIdx.x * 1024 + t * 4;
    int v[4]; int s = 0;
    #pragma unroll
    for (int i = 0; i < 4; i++) {
        int idx = base + i;
        v[i] = (idx < N) ? cnt[idx] : 0;
        s += v[i];
    }
    sh[t] = s;
    __syncthreads();
    #pragma unroll
    for (int d = 1; d < 256; d <<= 1) {
        int u = (t >= d) ? sh[t - d] : 0;
        __syncthreads();
        sh[t] += u;
        __syncthreads();
    }
    int run = bbase[blockIdx.x] + sh[t] - s;    // exclusive base for this thread
    #pragma unroll
    for (int i = 0; i < 4; i++) {
        int idx = base + i;
        if (idx < N) { off[idx] = run; cur[idx] = run; run += v[i]; }
    }
}

__global__ void fill_kernel(const int* __restrict__ ei, int* cur, int* csr, int E) {
    int e = blockIdx.x * blockDim.x + threadIdx.x;
    if (e < E) {
        int d = ei[E + e];
        int p = atomicAdd(&cur[d], 1);
        csr[p] = ei[e];
    }
}

// ================= aggregation: agg[n] = x[n] + sum_{s in csr[n]} x[s] ======
// One warp per node; lane owns 4 columns (float4). Unroll 4 edges for MLP.
__global__ void agg_csr_kernel(const float* __restrict__ x,
                               const int* __restrict__ off,
                               const int* __restrict__ csr,
                               float* __restrict__ agg, int M) {
    int warp = (blockIdx.x * blockDim.x + threadIdx.x) >> 5;
    int lane = threadIdx.x & 31;
    if (warp >= M) return;
    int beg = off[warp], end = off[warp + 1];
    const float4* xr = reinterpret_cast<const float4*>(x);
    float4 sum = xr[(size_t)warp * 32 + lane];
    int e = beg;
    for (; e + 3 < end; e += 4) {
        int s0 = csr[e], s1 = csr[e + 1], s2 = csr[e + 2], s3 = csr[e + 3];
        float4 v0 = xr[(size_t)s0 * 32 + lane];
        float4 v1 = xr[(size_t)s1 * 32 + lane];
        float4 v2 = xr[(size_t)s2 * 32 + lane];
        float4 v3 = xr[(size_t)s3 * 32 + lane];
        sum.x += (v0.x + v1.x) + (v2.x + v3.x);
        sum.y += (v0.y + v1.y) + (v2.y + v3.y);
        sum.z += (v0.z + v1.z) + (v2.z + v3.z);
        sum.w += (v0.w + v1.w) + (v2.w + v3.w);
    }
    for (; e < end; e++) {
        int s = csr[e];
        float4 v = xr[(size_t)s * 32 + lane];
        sum.x += v.x; sum.y += v.y; sum.z += v.z; sum.w += v.w;
    }
    reinterpret_cast<float4*>(agg)[(size_t)warp * 32 + lane] = sum;
}

// ---------------- W prep: W[k][n] fp32 -> W^T hi/lo bf16 padded images ------
struct WPtrs { const float* p[6]; };
__global__ void wprep_kernel(WPtrs wp, __nv_bfloat16* img) {
    int t = blockIdx.x * blockDim.x + threadIdx.x;
    if (t >= 6 * 16384) return;
    int g = t >> 14;
    int rem = t & 16383;
    int n = rem >> 7;
    int k = rem & 127;
    float w = wp.p[g][k * D + n];
    __nv_bfloat16 hi = __float2bfloat16(w);
    float r = w - __bfloat162float(hi);
    __nv_bfloat16 lo = __float2bfloat16(r);
    size_t base = (size_t)g * 2 * IMG_ELEMS;
    img[base + n * 136 + k]             = hi;
    img[base + IMG_ELEMS + n * 136 + k] = lo;
}

// ---------------- GEMM via mma.sync bf16, 3-term split ----------------------
__global__ __launch_bounds__(256, 1) void gemm_mma_kernel(
    const float* __restrict__ A, const __nv_bfloat16* __restrict__ Wimg,
    const float* __restrict__ bias, float* __restrict__ C, int M) {
    extern __shared__ char smem[];
    uint32_t sb = smem_u32(smem);
    int tid = threadIdx.x, wid = tid >> 5, lane = tid & 31;
    int row0 = blockIdx.x << 7;

    {
        const uint4* src = reinterpret_cast<const uint4*>(Wimg);
        uint4* dst = reinterpret_cast<uint4*>(smem);
        #pragma unroll
        for (int i = 0; i < 17; i++) dst[tid + i * 256] = src[tid + i * 256];
    }
    if (tid < 32)
        reinterpret_cast<float4*>(smem + OFF_BIAS)[tid] =
            reinterpret_cast<const float4*>(bias)[tid];

    #pragma unroll
    for (int i = 0; i < 8; i++) {
        int ci = tid + i * 256;
        int row = ci >> 4;
        int kg = ci & 15;
        int grow = row0 + row;
        uint32_t hi[4] = {0, 0, 0, 0}, lo[4] = {0, 0, 0, 0};
        if (grow < M) {
            const float4* ap = reinterpret_cast<const float4*>(A + (size_t)grow * D + kg * 8);
            float4 v0 = ap[0], v1 = ap[1];
            float a0[8] = {v0.x, v0.y, v0.z, v0.w, v1.x, v1.y, v1.z, v1.w};
            #pragma unroll
            for (int j = 0; j < 4; j++) {
                __nv_bfloat162 h = __floats2bfloat162_rn(a0[2 * j], a0[2 * j + 1]);
                float r0 = a0[2 * j]     - __bfloat162float(h.x);
                float r1 = a0[2 * j + 1] - __bfloat162float(h.y);
                __nv_bfloat162 l = __floats2bfloat162_rn(r0, r1);
                hi[j] = *reinterpret_cast<uint32_t*>(&h);
                lo[j] = *reinterpret_cast<uint32_t*>(&l);
            }
        }
        uint32_t off = row * ROWB + kg * 16;
        *reinterpret_cast<uint4*>(smem + OFF_AHI + off) = make_uint4(hi[0], hi[1], hi[2], hi[3]);
        *reinterpret_cast<uint4*>(smem + OFF_ALO + off) = make_uint4(lo[0], lo[1], lo[2], lo[3]);
    }
    __syncthreads();

    float acc[16][4];
    #pragma unroll
    for (int nb = 0; nb < 16; nb++)
        #pragma unroll
        for (int j = 0; j < 4; j++) acc[nb][j] = 0.0f;

    uint32_t aBase = sb + OFF_AHI + (wid * 16 + (lane & 15)) * ROWB + (lane >> 4) * 16;
    uint32_t wBase = sb + OFF_WHI + (lane & 7) * ROWB + ((lane & 8) ? 16 : 0);

    #pragma unroll
    for (int kc = 0; kc < 8; kc++) {
        uint32_t aHi[4], aLo[4];
        uint32_t aAddr = aBase + kc * 32;
        LDSM_X4(aHi[0], aHi[1], aHi[2], aHi[3], aAddr);
        LDSM_X4(aLo[0], aLo[1], aLo[2], aLo[3], aAddr + (OFF_ALO - OFF_AHI));
        #pragma unroll
        for (int nb = 0; nb < 16; nb++) {
            uint32_t bAddr = wBase + nb * (8 * ROWB) + kc * 32;
            uint32_t bHi0, bHi1, bLo0, bLo1;
            LDSM_X2(bHi0, bHi1, bAddr);
            LDSM_X2(bLo0, bLo1, bAddr + IMG_BYTES);
            mma_bf16(acc[nb], aHi, bHi0, bHi1);
            mma_bf16(acc[nb], aHi, bLo0, bLo1);
            mma_bf16(acc[nb], aLo, bHi0, bHi1);
        }
    }

    const float* sBias = reinterpret_cast<const float*>(smem + OFF_BIAS);
    int r0 = row0 + wid * 16 + (lane >> 2);
    int r1 = r0 + 8;
    #pragma unroll
    for (int nb = 0; nb < 16; nb++) {
        int cb = nb * 8 + (lane & 3) * 2;
        float b0 = sBias[cb], b1 = sBias[cb + 1];
        if (r0 < M) {
            float2 o;
            o.x = fmaxf(acc[nb][0] + b0, 0.f);
            o.y = fmaxf(acc[nb][1] + b1, 0.f);
            *reinterpret_cast<float2*>(C + (size_t)r0 * D + cb) = o;
        }
        if (r1 < M) {
            float2 o;
            o.x = fmaxf(acc[nb][2] + b0, 0.f);
            o.y = fmaxf(acc[nb][3] + b1, 0.f);
            *reinterpret_cast<float2*>(C + (size_t)r1 * D + cb) = o;
        }
    }
}

extern "C" void kernel_launch(void* const* d_in, const int* in_sizes, int n_in,
                              void* d_out, int out_size) {
    const float* x  = (const float*)d_in[0];
    const int*   ei = (const int*)d_in[1];   // int32 (JAX x64 disabled)
    const float* W1[3] = {(const float*)d_in[2],  (const float*)d_in[6],  (const float*)d_in[10]};
    const float* b1[3] = {(const float*)d_in[3],  (const float*)d_in[7],  (const float*)d_in[11]};
    const float* W2[3] = {(const float*)d_in[4],  (const float*)d_in[8],  (const float*)d_in[12]};
    const float* b2[3] = {(const float*)d_in[5],  (const float*)d_in[9],  (const float*)d_in[13]};

    int M = in_sizes[0] / D;
    int E = in_sizes[1] / 2;

    float *agg, *h, *t;
    __nv_bfloat16* wimg;
    int *cnt, *off, *cur, *csr, *bsum, *bbase;
    cudaGetSymbolAddress((void**)&agg,   g_agg);
    cudaGetSymbolAddress((void**)&h,     g_h);
    cudaGetSymbolAddress((void**)&t,     g_t);
    cudaGetSymbolAddress((void**)&wimg,  g_Wimg);
    cudaGetSymbolAddress((void**)&cnt,   g_cnt);
    cudaGetSymbolAddress((void**)&off,   g_off);
    cudaGetSymbolAddress((void**)&cur,   g_cur);
    cudaGetSymbolAddress((void**)&csr,   g_csr);
    cudaGetSymbolAddress((void**)&bsum,  g_bsum);
    cudaGetSymbolAddress((void**)&bbase, g_bbase);

    cudaFuncSetAttribute(gemm_mma_kernel, cudaFuncAttributeMaxDynamicSharedMemorySize, SMEM_TOTAL);

    // W images (order: W1_0, W2_0, W1_1, W2_1, W1_2, W2_2)
    WPtrs wp;
    wp.p[0] = W1[0]; wp.p[1] = W2[0];
    wp.p[2] = W1[1]; wp.p[3] = W2[1];
    wp.p[4] = W1[2]; wp.p[5] = W2[2];
    wprep_kernel<<<(6 * 16384 + 255) / 256, 256>>>(wp, wimg);

    // CSR build (edges identical across layers)
    int NB = (M + 1023) / 1024;            // 98 for M=100000 (<=128 required)
    zero_cnt_kernel<<<(M + 255) / 256, 256>>>(cnt, M);
    hist_kernel<<<(E + 255) / 256, 256>>>(ei, cnt, E);
    scan1_kernel<<<NB, 256>>>(cnt, bsum, M);
    scan2_kernel<<<1, 128>>>(bsum, bbase, NB, off, M, E);
    scan3_kernel<<<NB, 256>>>(cnt, bbase, off, cur, M);
    fill_kernel<<<(E + 255) / 256, 256>>>(ei, cur, csr, E);

    int aggBlocks = (M * 32 + 255) / 256;  // warp per node
    int gemmBlocks = (M + 127) / 128;

    const float* curx = x;
    float* outs[3] = {t, t, (float*)d_out};

    for (int l = 0; l < 3; l++) {
        agg_csr_kernel<<<aggBlocks, 256>>>(curx, off, csr, agg, M);
        gemm_mma_kernel<<<gemmBlocks, 256, SMEM_TOTAL>>>(
            agg, wimg + (size_t)(2 * l) * 2 * IMG_ELEMS, b1[l], h, M);
        gemm_mma_kernel<<<gemmBlocks, 256, SMEM_TOTAL>>>(
            h, wimg + (size_t)(2 * l + 1) * 2 * IMG_ELEMS, b2[l], outs[l], M);
        curx = outs[l];
    }
}

// round 6
// speedup vs baseline: 3.3040x; 1.2650x over previous
#include <cuda_runtime.h>
#include <cuda_bf16.h>
#include <cstdint>

#define D 128
#define MAXN 100000
#define MAXE 1600000

// ---------------- device scratch (allocation-free rule) --------------------
__device__ float g_agg[(size_t)MAXN * D];
__device__ float g_h  [(size_t)MAXN * D];
__device__ float g_t  [(size_t)MAXN * D];
// CSR scratch
__device__ int g_cnt[MAXN];
__device__ int g_off[MAXN + 1];
__device__ int g_cur[MAXN];
__device__ int g_csr[MAXE];
__device__ int g_bsum[128];
__device__ int g_bbase[128];
// 6 GEMMs x (hi + lo) W^T images, padded row-major [n][136] bf16
#define IMG_ELEMS 17408            // 128 * 136
__device__ __nv_bfloat16 g_Wimg[6 * 2 * IMG_ELEMS];

// ---------------- smem layout for gemm (bytes) ------------------------------
#define ROWB      272              // 136 bf16 per row
#define IMG_BYTES 34816            // 128 * 272 (W image) ; A image = 64*272 = 17408
#define OFF_WHI   0
#define OFF_WLO   34816
#define OFF_AHI   69632
#define OFF_ALO   87040
#define OFF_BIAS  104448
#define SMEM_TOTAL 104960

__device__ __forceinline__ uint32_t smem_u32(const void* p) {
    uint32_t a;
    asm("{ .reg .u64 t; cvta.to.shared.u64 t, %1; cvt.u32.u64 %0, t; }" : "=r"(a) : "l"(p));
    return a;
}

#define LDSM_X4(r0, r1, r2, r3, addr) \
    asm volatile("ldmatrix.sync.aligned.m8n8.x4.shared.b16 {%0,%1,%2,%3}, [%4];" \
                 : "=r"(r0), "=r"(r1), "=r"(r2), "=r"(r3) : "r"(addr))

#define CP_ASYNC16(dst, src) \
    asm volatile("cp.async.cg.shared.global [%0], [%1], 16;" :: "r"(dst), "l"(src))
#define CP_WAIT() asm volatile("cp.async.wait_all;" ::: "memory")

__device__ __forceinline__ void mma_bf16(float* c, const uint32_t* a, uint32_t b0, uint32_t b1) {
    asm volatile(
        "mma.sync.aligned.m16n8k16.row.col.f32.bf16.bf16.f32 "
        "{%0,%1,%2,%3}, {%4,%5,%6,%7}, {%8,%9}, {%0,%1,%2,%3};"
        : "+f"(c[0]), "+f"(c[1]), "+f"(c[2]), "+f"(c[3])
        : "r"(a[0]), "r"(a[1]), "r"(a[2]), "r"(a[3]), "r"(b0), "r"(b1));
}

// ================= CSR build =================================================
__global__ void zero_cnt_kernel(int* cnt, int N) {
    int i = blockIdx.x * blockDim.x + threadIdx.x;
    if (i < N) cnt[i] = 0;
}

__global__ void hist_kernel(const int* __restrict__ ei, int* cnt, int E) {
    int e = blockIdx.x * blockDim.x + threadIdx.x;
    if (e < E) atomicAdd(&cnt[ei[E + e]], 1);
}

__global__ void scan1_kernel(const int* __restrict__ cnt, int* bsum, int N) {
    __shared__ int sh[256];
    int t = threadIdx.x;
    int base = blockIdx.x * 1024 + t * 4;
    int s = 0;
    #pragma unroll
    for (int i = 0; i < 4; i++) { int idx = base + i; if (idx < N) s += cnt[idx]; }
    sh[t] = s;
    __syncthreads();
    for (int off = 128; off > 0; off >>= 1) {
        if (t < off) sh[t] += sh[t + off];
        __syncthreads();
    }
    if (t == 0) bsum[blockIdx.x] = sh[0];
}

__global__ void scan2_kernel(const int* __restrict__ bsum, int* bbase, int NB,
                             int* off, int N, int E) {
    __shared__ int sh[128];
    int t = threadIdx.x;
    int v = (t < NB) ? bsum[t] : 0;
    sh[t] = v;
    __syncthreads();
    #pragma unroll
    for (int d = 1; d < 128; d <<= 1) {
        int u = (t >= d) ? sh[t - d] : 0;
        __syncthreads();
        sh[t] += u;
        __syncthreads();
    }
    if (t < NB) bbase[t] = sh[t] - v;
    if (t == 0) off[N] = E;
}

__global__ void scan3_kernel(const int* __restrict__ cnt, const int* __restrict__ bbase,
                             int* off, int* cur, int N) {
    __shared__ int sh[256];
    int t = threadIdx.x;
    int base = blockIdx.x * 1024 + t * 4;
    int v[4]; int s = 0;
    #pragma unroll
    for (int i = 0; i < 4; i++) {
        int idx = base + i;
        v[i] = (idx < N) ? cnt[idx] : 0;
        s += v[i];
    }
    sh[t] = s;
    __syncthreads();
    #pragma unroll
    for (int d = 1; d < 256; d <<= 1) {
        int u = (t >= d) ? sh[t - d] : 0;
        __syncthreads();
        sh[t] += u;
        __syncthreads();
    }
    int run = bbase[blockIdx.x] + sh[t] - s;
    #pragma unroll
    for (int i = 0; i < 4; i++) {
        int idx = base + i;
        if (idx < N) { off[idx] = run; cur[idx] = run; run += v[i]; }
    }
}

__global__ void fill_kernel(const int* __restrict__ ei, int* cur, int* csr, int E) {
    int e = blockIdx.x * blockDim.x + threadIdx.x;
    if (e < E) {
        int d = ei[E + e];
        int p = atomicAdd(&cur[d], 1);
        csr[p] = ei[e];
    }
}

// ================= aggregation: agg[n] = x[n] + sum_{s in csr[n]} x[s] ======
__global__ void agg_csr_kernel(const float* __restrict__ x,
                               const int* __restrict__ off,
                               const int* __restrict__ csr,
                               float* __restrict__ agg, int M) {
    int warp = (blockIdx.x * blockDim.x + threadIdx.x) >> 5;
    int lane = threadIdx.x & 31;
    if (warp >= M) return;
    int beg = off[warp], end = off[warp + 1];
    const float4* xr = reinterpret_cast<const float4*>(x);
    float4 sum = xr[(size_t)warp * 32 + lane];
    int e = beg;
    for (; e + 3 < end; e += 4) {
        int s0 = csr[e], s1 = csr[e + 1], s2 = csr[e + 2], s3 = csr[e + 3];
        float4 v0 = xr[(size_t)s0 * 32 + lane];
        float4 v1 = xr[(size_t)s1 * 32 + lane];
        float4 v2 = xr[(size_t)s2 * 32 + lane];
        float4 v3 = xr[(size_t)s3 * 32 + lane];
        sum.x += (v0.x + v1.x) + (v2.x + v3.x);
        sum.y += (v0.y + v1.y) + (v2.y + v3.y);
        sum.z += (v0.z + v1.z) + (v2.z + v3.z);
        sum.w += (v0.w + v1.w) + (v2.w + v3.w);
    }
    for (; e < end; e++) {
        int s = csr[e];
        float4 v = xr[(size_t)s * 32 + lane];
        sum.x += v.x; sum.y += v.y; sum.z += v.z; sum.w += v.w;
    }
    reinterpret_cast<float4*>(agg)[(size_t)warp * 32 + lane] = sum;
}

// ---------------- W prep: W[k][n] fp32 -> W^T hi/lo bf16 padded images ------
struct WPtrs { const float* p[6]; };
__global__ void wprep_kernel(WPtrs wp, __nv_bfloat16* img) {
    int t = blockIdx.x * blockDim.x + threadIdx.x;
    if (t >= 6 * 16384) return;
    int g = t >> 14;
    int rem = t & 16383;
    int n = rem >> 7;
    int k = rem & 127;
    float w = wp.p[g][k * D + n];
    __nv_bfloat16 hi = __float2bfloat16(w);
    float r = w - __bfloat162float(hi);
    __nv_bfloat16 lo = __float2bfloat16(r);
    size_t base = (size_t)g * 2 * IMG_ELEMS;
    img[base + n * 136 + k]             = hi;
    img[base + IMG_ELEMS + n * 136 + k] = lo;
}

// ---------------- GEMM via mma.sync bf16, 3-term split ----------------------
// Block: 256 threads (8 warps), 64-row x 128-col output tile, 2 CTAs/SM.
// Warp grid 4x2: warp w -> rows (w&3)*16, cols (w>>2)*64.
__global__ __launch_bounds__(256, 2) void gemm_mma_kernel(
    const float* __restrict__ A, const __nv_bfloat16* __restrict__ Wimg,
    const float* __restrict__ bias, float* __restrict__ C, int M) {
    extern __shared__ char smem[];
    uint32_t sb = smem_u32(smem);
    int tid = threadIdx.x, wid = tid >> 5, lane = tid & 31;
    int row0 = blockIdx.x << 6;

    // W hi+lo images: 69632 B contiguous in gmem -> cp.async (overlaps A convert)
    {
        const char* src = reinterpret_cast<const char*>(Wimg);
        #pragma unroll
        for (int i = 0; i < 17; i++) {
            uint32_t off = (tid + i * 256) * 16;
            CP_ASYNC16(sb + OFF_WHI + off, src + off);
        }
    }
    if (tid < 32)
        reinterpret_cast<float4*>(smem + OFF_BIAS)[tid] =
            reinterpret_cast<const float4*>(bias)[tid];

    // Convert A tile (64 rows x 128 k fp32) -> hi/lo bf16 padded images
    #pragma unroll
    for (int i = 0; i < 4; i++) {
        int ci = tid + i * 256;          // 0..1023
        int row = ci >> 4;
        int kg = ci & 15;
        int grow = row0 + row;
        uint32_t hi[4] = {0, 0, 0, 0}, lo[4] = {0, 0, 0, 0};
        if (grow < M) {
            const float4* ap = reinterpret_cast<const float4*>(A + (size_t)grow * D + kg * 8);
            float4 v0 = ap[0], v1 = ap[1];
            float a0[8] = {v0.x, v0.y, v0.z, v0.w, v1.x, v1.y, v1.z, v1.w};
            #pragma unroll
            for (int j = 0; j < 4; j++) {
                __nv_bfloat162 h = __floats2bfloat162_rn(a0[2 * j], a0[2 * j + 1]);
                float r0 = a0[2 * j]     - __bfloat162float(h.x);
                float r1 = a0[2 * j + 1] - __bfloat162float(h.y);
                __nv_bfloat162 l = __floats2bfloat162_rn(r0, r1);
                hi[j] = *reinterpret_cast<uint32_t*>(&h);
                lo[j] = *reinterpret_cast<uint32_t*>(&l);
            }
        }
        uint32_t off = row * ROWB + kg * 16;
        *reinterpret_cast<uint4*>(smem + OFF_AHI + off) = make_uint4(hi[0], hi[1], hi[2], hi[3]);
        *reinterpret_cast<uint4*>(smem + OFF_ALO + off) = make_uint4(lo[0], lo[1], lo[2], lo[3]);
    }
    CP_WAIT();
    __syncthreads();

    int wg_row = wid & 3, wg_col = wid >> 2;

    // Accumulators: 8 n-blocks x 4 regs
    float acc[8][4];
    #pragma unroll
    for (int nb = 0; nb < 8; nb++)
        #pragma unroll
        for (int j = 0; j < 4; j++) acc[nb][j] = 0.0f;

    // A x4: lanes 0-15 rows, lanes 16-31 k+8
    uint32_t aBase = sb + OFF_AHI + (wg_row * 16 + (lane & 15)) * ROWB + (lane >> 4) * 16;
    // B x4: m0 rows n0..7 k0 | m1 rows n0..7 k+8 | m2 rows n0+8..15 k0 | m3 rows n0+8..15 k+8
    uint32_t wBase = sb + OFF_WHI
                   + (wg_col * 64 + ((lane >> 4) << 3) + (lane & 7)) * ROWB
                   + ((lane >> 3) & 1) * 16;

    #pragma unroll
    for (int kc = 0; kc < 8; kc++) {
        uint32_t aHi[4], aLo[4];
        uint32_t aAddr = aBase + kc * 32;
        LDSM_X4(aHi[0], aHi[1], aHi[2], aHi[3], aAddr);
        LDSM_X4(aLo[0], aLo[1], aLo[2], aLo[3], aAddr + (OFF_ALO - OFF_AHI));
        #pragma unroll
        for (int nbp = 0; nbp < 4; nbp++) {
            uint32_t bAddr = wBase + nbp * (16 * ROWB) + kc * 32;
            uint32_t bh0, bh1, bh2, bh3, bl0, bl1, bl2, bl3;
            LDSM_X4(bh0, bh1, bh2, bh3, bAddr);
            LDSM_X4(bl0, bl1, bl2, bl3, bAddr + IMG_BYTES);
            mma_bf16(acc[2 * nbp],     aHi, bh0, bh1);
            mma_bf16(acc[2 * nbp],     aHi, bl0, bl1);
            mma_bf16(acc[2 * nbp],     aLo, bh0, bh1);
            mma_bf16(acc[2 * nbp + 1], aHi, bh2, bh3);
            mma_bf16(acc[2 * nbp + 1], aHi, bl2, bl3);
            mma_bf16(acc[2 * nbp + 1], aLo, bh2, bh3);
        }
    }

    // Epilogue
    const float* sBias = reinterpret_cast<const float*>(smem + OFF_BIAS);
    int r0 = row0 + wg_row * 16 + (lane >> 2);
    int r1 = r0 + 8;
    #pragma unroll
    for (int nb = 0; nb < 8; nb++) {
        int cb = wg_col * 64 + nb * 8 + (lane & 3) * 2;
        float b0 = sBias[cb], b1 = sBias[cb + 1];
        if (r0 < M) {
            float2 o;
            o.x = fmaxf(acc[nb][0] + b0, 0.f);
            o.y = fmaxf(acc[nb][1] + b1, 0.f);
            *reinterpret_cast<float2*>(C + (size_t)r0 * D + cb) = o;
        }
        if (r1 < M) {
            float2 o;
            o.x = fmaxf(acc[nb][2] + b0, 0.f);
            o.y = fmaxf(acc[nb][3] + b1, 0.f);
            *reinterpret_cast<float2*>(C + (size_t)r1 * D + cb) = o;
        }
    }
}

extern "C" void kernel_launch(void* const* d_in, const int* in_sizes, int n_in,
                              void* d_out, int out_size) {
    const float* x  = (const float*)d_in[0];
    const int*   ei = (const int*)d_in[1];   // int32 (JAX x64 disabled)
    const float* W1[3] = {(const float*)d_in[2],  (const float*)d_in[6],  (const float*)d_in[10]};
    const float* b1[3] = {(const float*)d_in[3],  (const float*)d_in[7],  (const float*)d_in[11]};
    const float* W2[3] = {(const float*)d_in[4],  (const float*)d_in[8],  (const float*)d_in[12]};
    const float* b2[3] = {(const float*)d_in[5],  (const float*)d_in[9],  (const float*)d_in[13]};

    int M = in_sizes[0] / D;
    int E = in_sizes[1] / 2;

    float *agg, *h, *t;
    __nv_bfloat16* wimg;
    int *cnt, *off, *cur, *csr, *bsum, *bbase;
    cudaGetSymbolAddress((void**)&agg,   g_agg);
    cudaGetSymbolAddress((void**)&h,     g_h);
    cudaGetSymbolAddress((void**)&t,     g_t);
    cudaGetSymbolAddress((void**)&wimg,  g_Wimg);
    cudaGetSymbolAddress((void**)&cnt,   g_cnt);
    cudaGetSymbolAddress((void**)&off,   g_off);
    cudaGetSymbolAddress((void**)&cur,   g_cur);
    cudaGetSymbolAddress((void**)&csr,   g_csr);
    cudaGetSymbolAddress((void**)&bsum,  g_bsum);
    cudaGetSymbolAddress((void**)&bbase, g_bbase);

    cudaFuncSetAttribute(gemm_mma_kernel, cudaFuncAttributeMaxDynamicSharedMemorySize, SMEM_TOTAL);

    // W images (order: W1_0, W2_0, W1_1, W2_1, W1_2, W2_2)
    WPtrs wp;
    wp.p[0] = W1[0]; wp.p[1] = W2[0];
    wp.p[2] = W1[1]; wp.p[3] = W2[1];
    wp.p[4] = W1[2]; wp.p[5] = W2[2];
    wprep_kernel<<<(6 * 16384 + 255) / 256, 256>>>(wp, wimg);

    // CSR build (edges identical across layers)
    int NB = (M + 1023) / 1024;
    zero_cnt_kernel<<<(M + 255) / 256, 256>>>(cnt, M);
    hist_kernel<<<(E + 255) / 256, 256>>>(ei, cnt, E);
    scan1_kernel<<<NB, 256>>>(cnt, bsum, M);
    scan2_kernel<<<1, 128>>>(bsum, bbase, NB, off, M, E);
    scan3_kernel<<<NB, 256>>>(cnt, bbase, off, cur, M);
    fill_kernel<<<(E + 255) / 256, 256>>>(ei, cur, csr, E);

    int aggBlocks = (M * 32 + 255) / 256;
    int gemmBlocks = (M + 63) / 64;

    const float* curx = x;
    float* outs[3] = {t, t, (float*)d_out};

    for (int l = 0; l < 3; l++) {
        agg_csr_kernel<<<aggBlocks, 256>>>(curx, off, csr, agg, M);
        gemm_mma_kernel<<<gemmBlocks, 256, SMEM_TOTAL>>>(
            agg, wimg + (size_t)(2 * l) * 2 * IMG_ELEMS, b1[l], h, M);
        gemm_mma_kernel<<<gemmBlocks, 256, SMEM_TOTAL>>>(
            h, wimg + (size_t)(2 * l + 1) * 2 * IMG_ELEMS, b2[l], outs[l], M);
        curx = outs[l];
    }
}